// round 2
// baseline (speedup 1.0000x reference)
#include <cuda_runtime.h>

#define NTRI 69

// ---------------- device-global precomputed tables (filled by init kernels each launch) ----
__device__ int d_tl1[NTRI], d_tl2[NTRI], d_tl[NTRI], d_tbase[NTRI];        // TRIPLES order
__device__ int d_f1off[NTRI], d_f2off[NTRI], d_cgbase[NTRI], d_nl1[NTRI], d_nl2[NTRI]; // grouped by l
__device__ float d_cg[3600];        // dense CG blocks, 3587 used
__device__ float d_invstd[4416];    // 1/(moving_std+eps)

// Compile-time per-l constants (derived from MAXL=5, TAUS=8) — device-visible
__device__ constexpr int NT_D[6]     = {384, 640, 832, 896, 896, 768};       // MIDDLE_TAUS
__device__ constexpr int STDOFF_D[6] = {0, 384, 1024, 1856, 2752, 3648};
__device__ constexpr int WOFF_D[6]   = {0, 3072, 8192, 14848, 22016, 29184}; // complex units
__device__ constexpr int ACTOFF_D[6] = {0, 8, 32, 72, 128, 200};             // complex units
__device__ constexpr int LSTART_D[6] = {0, 6, 16, 29, 43, 57};               // triple group starts per l
// max smem mid size: l=5 -> 11*(768+1) = 8459 complex
#define MID_MAX 8459

// ---------------- init kernels -------------------------------------------------------------
__global__ void k_meta() {
  if (threadIdx.x != 0 || blockIdx.x != 0) return;
  int n = 0;
  for (int a = 0; a <= 5; a++)
    for (int b = 0; b <= a; b++) {
      int lmax = (a + b < 5) ? (a + b) : 5;
      for (int l = a - b; l <= lmax; l++) { d_tl1[n] = a; d_tl2[n] = b; d_tl[n] = l; n++; }
    }
  int cg = 0;
  for (int i = 0; i < NTRI; i++) { d_tbase[i] = cg; cg += (2 * d_tl1[i] + 1) * (2 * d_tl2[i] + 1); }
  const int actoff[6] = {0, 8, 32, 72, 128, 200};
  int d = 0;
  for (int l = 0; l <= 5; l++)
    for (int i = 0; i < NTRI; i++)
      if (d_tl[i] == l) {
        d_f1off[d] = actoff[d_tl1[i]];
        d_f2off[d] = actoff[d_tl2[i]];
        d_cgbase[d] = d_tbase[i];
        d_nl1[d] = 2 * d_tl1[i] + 1;
        d_nl2[d] = 2 * d_tl2[i] + 1;
        d++;
      }
}

__device__ __forceinline__ double dfact(int n) {
  double r = 1.0;
  for (int i = 2; i <= n; i++) r *= (double)i;
  return r;
}

__global__ void k_cg() {
  const int tr = blockIdx.x;
  const int l1 = d_tl1[tr], l2 = d_tl2[tr], l = d_tl[tr];
  const int nl2 = 2 * l2 + 1;
  const int tot = (2 * l1 + 1) * nl2;
  const int base = d_tbase[tr];
  for (int slot = threadIdx.x; slot < tot; slot += blockDim.x) {
    const int m1 = slot / nl2 - l1;
    const int m2 = slot % nl2 - l2;
    const int m = m1 + m2;
    double v = 0.0;
    if (m >= -l && m <= l) {
      double pre = sqrt((double)(2 * l + 1) * dfact(l + l1 - l2) * dfact(l - l1 + l2) *
                        dfact(l1 + l2 - l) / dfact(l1 + l2 + l + 1));
      pre *= sqrt(dfact(l + m) * dfact(l - m) * dfact(l1 - m1) * dfact(l1 + m1) *
                  dfact(l2 - m2) * dfact(l2 + m2));
      double s = 0.0;
      for (int k = 0; k <= l1 + l2 - l; k++) {
        int e2 = l1 + l2 - l - k, e3 = l1 - m1 - k, e4 = l2 + m2 - k;
        int e5 = l - l2 + m1 + k, e6 = l - l1 - m2 + k;
        if (e3 < 0 || e4 < 0 || e5 < 0 || e6 < 0) continue;
        s += ((k & 1) ? -1.0 : 1.0) /
             (dfact(k) * dfact(e2) * dfact(e3) * dfact(e4) * dfact(e5) * dfact(e6));
      }
      v = pre * s;
    }
    d_cg[base + slot] = (float)v;
  }
}

__global__ void k_invstd(const float* __restrict__ s) {
  int i = blockIdx.x * blockDim.x + threadIdx.x;
  if (i < 4416) d_invstd[i] = 1.0f / (s[i] + 1e-5f);
}

// ---------------- main fused kernel --------------------------------------------------------
// One CTA per batch element. Per l: stage A (CG -> smem mid, scaled by 1/std),
// stage B (warp w owns output tau o=w, register accumulators, shfl reduce).
extern __shared__ float2 smf[];

__global__ __launch_bounds__(256) void k_fused(const float2* __restrict__ act,
                                               const float2* __restrict__ wts,
                                               float2* __restrict__ out) {
  const int b = blockIdx.x;
  const int tid = threadIdx.x;
  const int lane = tid & 31, warp = tid >> 5;
  float2* Fs = smf;         // 288 complex activations for this batch element
  float2* mid = smf + 288;  // up to MID_MAX complex

  for (int i = tid; i < 288; i += 256) Fs[i] = act[b * 288 + i];
  __syncthreads();

#pragma unroll
  for (int l = 0; l < 6; l++) {
    const int nl = 2 * l + 1;
    const int nt = NT_D[l];
    const int stride = nt + 1;  // pad: word-stride mod 32 == 2 -> conflict-free m reads

    // ---- stage A: CG contraction, channel-parallel (warp stays inside one triple) ----
    for (int c = tid; c < nt; c += 256) {
      const int tr = LSTART_D[l] + (c >> 6);
      const int nl1 = d_nl1[tr], nl2 = d_nl2[tr];
      const int l1 = (nl1 - 1) >> 1, l2 = (nl2 - 1) >> 1;
      const int cgb = d_cgbase[tr];
      const float2* A = Fs + d_f1off[tr] + ((c >> 3) & 7) * nl1;
      const float2* Bp = Fs + d_f2off[tr] + (c & 7) * nl2;
      const float istd = d_invstd[STDOFF_D[l] + c];
      for (int m = 0; m < nl; m++) {
        const int ms = m - l;
        int lo = (-l1 > ms - l2) ? -l1 : ms - l2;
        int hi = (l1 < ms + l2) ? l1 : ms + l2;
        float ar = 0.f, ai = 0.f;
        for (int m1 = lo; m1 <= hi; m1++) {
          const float cgc = __ldg(&d_cg[cgb + (m1 + l1) * nl2 + (ms - m1 + l2)]);
          const float2 av = A[m1 + l1];
          const float2 bv = Bp[ms - m1 + l2];
          ar += cgc * (av.x * bv.x - av.y * bv.y);
          ai += cgc * (av.x * bv.y + av.y * bv.x);
        }
        mid[m * stride + c] = make_float2(ar * istd, ai * istd);
      }
    }
    __syncthreads();

    // ---- stage B: out[o,m] = sum_c W[o,c] * mid[m,c]; warp == o -------------------
    {
      const int o = warp;
      const float2* wp = wts + WOFF_D[l] + o * nt;
      float accr[11], acci[11];
#pragma unroll
      for (int m = 0; m < nl; m++) { accr[m] = 0.f; acci[m] = 0.f; }
      for (int c = lane; c < nt; c += 32) {
        const float2 wv = __ldg(wp + c);
#pragma unroll
        for (int m = 0; m < nl; m++) {
          const float2 mv = mid[m * stride + c];
          accr[m] += wv.x * mv.x - wv.y * mv.y;
          acci[m] += wv.x * mv.y + wv.y * mv.x;
        }
      }
#pragma unroll
      for (int m = 0; m < nl; m++) {
        float r = accr[m], im = acci[m];
        for (int off = 16; off; off >>= 1) {
          r += __shfl_xor_sync(0xffffffffu, r, off);
          im += __shfl_xor_sync(0xffffffffu, im, off);
        }
        if (lane == 0) out[b * 288 + ACTOFF_D[l] + o * nl + m] = make_float2(r, im);
      }
    }
    __syncthreads();
  }
}

// ---------------- launch -------------------------------------------------------------------
extern "C" void kernel_launch(void* const* d_in, const int* in_sizes, int n_in,
                              void* d_out, int out_size) {
  const float2* act = nullptr;
  const float2* wts = nullptr;
  const float* mstd = nullptr;
  int B = 1024;
  for (int i = 0; i < n_in; i++) {
    if (in_sizes[i] == 4416) mstd = (const float*)d_in[i];           // moving_std
    else if (in_sizes[i] == 70656) wts = (const float2*)d_in[i];     // weights [35328,2]
    else { act = (const float2*)d_in[i]; B = in_sizes[i] / 576; }    // activations [B,288,2]
  }
  float2* out = (float2*)d_out;

  k_meta<<<1, 1>>>();
  k_cg<<<NTRI, 128>>>();
  k_invstd<<<(4416 + 255) / 256, 256>>>(mstd);

  const int smem = (288 + MID_MAX) * (int)sizeof(float2);  // ~70 KB
  cudaFuncSetAttribute(k_fused, cudaFuncAttributeMaxDynamicSharedMemorySize, smem);
  k_fused<<<B, 256, smem>>>(act, wts, out);
}

// round 4
// speedup vs baseline: 1.3041x; 1.3041x over previous
#include <cuda_runtime.h>

// ===================== compile-time CG machinery (host+device constexpr) =====================
__host__ __device__ constexpr double cfact(int n) { double r = 1.0; for (int i = 2; i <= n; i++) r *= (double)i; return r; }
__host__ __device__ constexpr double csqrt_(double x) { double g = x > 1.0 ? x : 1.0; for (int i = 0; i < 100; i++) g = 0.5 * (g + x / g); return g; }
__host__ __device__ constexpr double cg_d(int l1, int l2, int l, int m1, int m2) {
  const int m = m1 + m2;
  if (m < -l || m > l) return 0.0;
  double pre = csqrt_((2 * l + 1) * cfact(l + l1 - l2) * cfact(l - l1 + l2) * cfact(l1 + l2 - l) / cfact(l1 + l2 + l + 1));
  pre *= csqrt_(cfact(l + m) * cfact(l - m) * cfact(l1 - m1) * cfact(l1 + m1) * cfact(l2 - m2) * cfact(l2 + m2));
  double s = 0.0;
  for (int k = 0; k <= l1 + l2 - l; k++) {
    int e2 = l1 + l2 - l - k, e3 = l1 - m1 - k, e4 = l2 + m2 - k, e5 = l - l2 + m1 + k, e6 = l - l1 - m2 + k;
    if (e3 < 0 || e4 < 0 || e5 < 0 || e6 < 0) continue;
    double d = cfact(k) * cfact(e2) * cfact(e3) * cfact(e4) * cfact(e5) * cfact(e6);
    s += ((k & 1) ? -1.0 : 1.0) / d;
  }
  double v = pre * s;
  if (v < 1e-12 && v > -1e-12) return 0.0;
  return v;
}
__host__ __device__ constexpr int lmax_of(int a, int b) { return (a + b < 5) ? (a + b) : 5; }
__host__ __device__ constexpr int NTA_f(int l)     { return l == 0 ? 384 : l == 1 ? 640 : l == 2 ? 832 : l == 3 ? 896 : l == 4 ? 896 : 768; }
__host__ __device__ constexpr int STDOFF_f(int l)  { return l == 0 ? 0 : l == 1 ? 384 : l == 2 ? 1024 : l == 3 ? 1856 : l == 4 ? 2752 : 3648; }
__host__ __device__ constexpr int WOFF_f(int l)    { return l == 0 ? 0 : l == 1 ? 3072 : l == 2 ? 8192 : l == 3 ? 14848 : l == 4 ? 22016 : 29184; }
__host__ __device__ constexpr int ACTOFF_f(int l)  { return l == 0 ? 0 : l == 1 ? 8 : l == 2 ? 32 : l == 3 ? 72 : l == 4 ? 128 : 200; }
__host__ __device__ constexpr int ACCOFF_f(int l)  { return l * l; }
__host__ __device__ constexpr int chanoff_f(int L, int l1, int l2) {
  int off = 0;
  for (int a = 0; a <= 5; a++)
    for (int b = 0; b <= a; b++) {
      int lm = lmax_of(a, b);
      for (int l = a - b; l <= lm; l++)
        if (l == L) { if (a == l1 && b == l2) return off; off += 64; }
    }
  return 0;
}
__host__ __device__ constexpr int sumnl_f(int a, int b) { int s = 0; for (int l = a - b; l <= lmax_of(a, b); l++) s += 2 * l + 1; return s; }

template <int L1, int L2>
struct PairCG {
  static constexpr int LMIN = L1 - L2, LMAX = lmax_of(L1, L2), NLS = LMAX - LMIN + 1;
  static constexpr int NL1 = 2 * L1 + 1, NL2 = 2 * L2 + 1;
  float v[NLS][NL1][NL2];
  int stdidx[NLS];
  int widx[NLS];
  int ntl[NLS];
  __host__ __device__ constexpr PairCG() : v(), stdidx(), widx(), ntl() {
    for (int li = 0; li < NLS; li++) {
      const int L = LMIN + li;
      for (int a = 0; a < NL1; a++)
        for (int c = 0; c < NL2; c++)
          v[li][a][c] = (float)cg_d(L1, L2, L, a - L1, c - L2);
      stdidx[li] = STDOFF_f(L) + chanoff_f(L, L1, L2);
      widx[li]   = WOFF_f(L) + chanoff_f(L, L1, L2);
      ntl[li]    = NTA_f(L);
    }
  }
};

// ===================== device globals =====================
__device__ float d_invstd[4416];

__global__ void k_invstd(const float* __restrict__ s) {
  int i = blockIdx.x * blockDim.x + threadIdx.x;
  if (i < 4416) d_invstd[i] = 1.0f / (s[i] + 1e-5f);
}

// ===================== stage A: one pair, 64 threads (thread = channel) =====================
template <int L1, int L2>
__device__ __forceinline__ void pairA(const float2* __restrict__ Fs, float2* __restrict__ blk, int ch) {
  constexpr PairCG<L1, L2> CG{};
  constexpr int NL1 = 2 * L1 + 1, NL2 = 2 * L2 + 1;
  constexpr int NLS = PairCG<L1, L2>::NLS, LMIN = L1 - L2;
  constexpr int NROW = sumnl_f(L1, L2);
  const int t = ch >> 3, s = ch & 7;
  const float2* Ap = Fs + ACTOFF_f(L1) + t * NL1;
  const float2* Bp = Fs + ACTOFF_f(L2) + s * NL2;
  float2 a[NL1];
#pragma unroll
  for (int i = 0; i < NL1; i++) a[i] = Ap[i];
  float2 frag[NROW];
#pragma unroll
  for (int i = 0; i < NROW; i++) { frag[i].x = 0.f; frag[i].y = 0.f; }
#pragma unroll
  for (int m2 = 0; m2 < NL2; m2++) {
    const float2 b = Bp[m2];
#pragma unroll
    for (int m1 = 0; m1 < NL1; m1++) {
      const float px = a[m1].x * b.x - a[m1].y * b.y;
      const float py = a[m1].x * b.y + a[m1].y * b.x;
#pragma unroll
      for (int li = 0; li < NLS; li++) {
        const int L = LMIN + li;
        const int midx = (m1 - L1) + (m2 - L2) + L;   // m + L
        if (midx >= 0 && midx < 2 * L + 1) {
          const float c = CG.v[li][m1][m2];
          if (c != 0.f) {
            const int rowoff = li * (2 * LMIN + li);  // sum of nl below li
            frag[rowoff + midx].x += c * px;
            frag[rowoff + midx].y += c * py;
          }
        }
      }
    }
  }
#pragma unroll
  for (int li = 0; li < NLS; li++) {
    const int L = LMIN + li;
    const int rowoff = li * (2 * LMIN + li);
    const float istd = d_invstd[CG.stdidx[li] + ch];
#pragma unroll
    for (int m = 0; m < 2 * L + 1; m++) {
      const float2 f = frag[rowoff + m];
      blk[(rowoff + m) * 64 + ch] = make_float2(f.x * istd, f.y * istd);
    }
  }
}

// ===================== stage B: one pair, all 8 warps (warp = output tau o) =====================
template <int L1, int L2>
__device__ __forceinline__ void pairB(const float2* __restrict__ blk, const float2* __restrict__ wts,
                                      float2 (&acc)[36], int o, int lane) {
  constexpr PairCG<L1, L2> CG{};
  constexpr int NLS = PairCG<L1, L2>::NLS, LMIN = L1 - L2;
#pragma unroll
  for (int li = 0; li < NLS; li++) {
    const int L = LMIN + li;
    const int rowoff = li * (2 * LMIN + li);
    const int wbase = CG.widx[li] + o * CG.ntl[li];
#pragma unroll
    for (int h = 0; h < 2; h++) {
      const int c = lane + 32 * h;
      const float2 w = __ldg(wts + wbase + c);
#pragma unroll
      for (int m = 0; m < 2 * L + 1; m++) {
        const float2 mv = blk[(rowoff + m) * 64 + c];
        acc[ACCOFF_f(L) + m].x += w.x * mv.x - w.y * mv.y;
        acc[ACCOFF_f(L) + m].y += w.x * mv.y + w.y * mv.x;
      }
    }
  }
}

// ===================== one round: 4 pairs (group g builds block g; all warps consume) ========
template <int A0, int B0, int A1, int B1, int A2, int B2, int A3, int B3>
__device__ __forceinline__ void do_round(const float2* __restrict__ Fs, float2* __restrict__ blk,
                                         const float2* __restrict__ wts, float2 (&acc)[36],
                                         int tid, int o, int lane) {
  const int grp = tid >> 6, ch = tid & 63;
  constexpr int O0 = 0;
  constexpr int O1 = O0 + sumnl_f(A0, B0);
  constexpr int O2 = O1 + sumnl_f(A1, B1);
  constexpr int O3 = O2 + sumnl_f(A2, B2);
  if (grp == 0)      pairA<A0, B0>(Fs, blk + O0 * 64, ch);
  else if (grp == 1) pairA<A1, B1>(Fs, blk + O1 * 64, ch);
  else if (grp == 2) pairA<A2, B2>(Fs, blk + O2 * 64, ch);
  else               pairA<A3, B3>(Fs, blk + O3 * 64, ch);
  __syncthreads();
  pairB<A0, B0>(blk + O0 * 64, wts, acc, o, lane);
  pairB<A1, B1>(blk + O1 * 64, wts, acc, o, lane);
  pairB<A2, B2>(blk + O2 * 64, wts, acc, o, lane);
  pairB<A3, B3>(blk + O3 * 64, wts, acc, o, lane);
  __syncthreads();
}

// ===================== fused kernel =====================
extern __shared__ float2 smem_[];

__global__ __launch_bounds__(256, 1) void k_fused(const float2* __restrict__ act,
                                                  const float2* __restrict__ wts,
                                                  float2* __restrict__ out) {
  const int b = blockIdx.x, tid = threadIdx.x;
  const int lane = tid & 31, o = tid >> 5;
  float2* Fs = smem_;        // 288 complex activations
  float2* blk = smem_ + 288; // up to 98*64 complex mid blocks per round

  for (int i = tid; i < 288; i += 256) Fs[i] = act[b * 288 + i];
  float2 acc[36];
#pragma unroll
  for (int i = 0; i < 36; i++) { acc[i].x = 0.f; acc[i].y = 0.f; }
  __syncthreads();

  do_round<3, 3, 5, 4, 2, 1, 5, 0>(Fs, blk, wts, acc, tid, o, lane);  // 36+35+15+11=97
  do_round<4, 4, 4, 3, 5, 1, 3, 0>(Fs, blk, wts, acc, tid, o, lane);  // 36+35+20+7=98
  do_round<5, 5, 5, 3, 2, 2, 2, 0>(Fs, blk, wts, acc, tid, o, lane);  // 36+32+25+5=98
  do_round<3, 2, 4, 2, 3, 1, 1, 1>(Fs, blk, wts, acc, tid, o, lane);  // 35+32+21+9=97
  do_round<4, 1, 5, 2, 4, 0, 1, 0>(Fs, blk, wts, acc, tid, o, lane);  // 27+27+9+3=66
  {                                                                    // final pair (0,0)
    const int grp = tid >> 6, ch = tid & 63;
    if (grp == 0) pairA<0, 0>(Fs, blk, ch);
    __syncthreads();
    pairB<0, 0>(blk, wts, acc, o, lane);
  }

  // epilogue: reduce lane partials, write output
#pragma unroll
  for (int L = 0; L < 6; L++) {
#pragma unroll
    for (int m = 0; m < 2 * L + 1; m++) {
      float2 v = acc[ACCOFF_f(L) + m];
#pragma unroll
      for (int off = 16; off; off >>= 1) {
        v.x += __shfl_xor_sync(0xffffffffu, v.x, off);
        v.y += __shfl_xor_sync(0xffffffffu, v.y, off);
      }
      if (lane == 0) out[b * 288 + ACTOFF_f(L) + o * (2 * L + 1) + m] = v;
    }
  }
}

// ===================== launch =====================
extern "C" void kernel_launch(void* const* d_in, const int* in_sizes, int n_in,
                              void* d_out, int out_size) {
  const float2* act = nullptr;
  const float2* wts = nullptr;
  const float* mstd = nullptr;
  int B = 1024;
  for (int i = 0; i < n_in; i++) {
    if (in_sizes[i] == 4416) mstd = (const float*)d_in[i];
    else if (in_sizes[i] == 70656) wts = (const float2*)d_in[i];
    else { act = (const float2*)d_in[i]; B = in_sizes[i] / 576; }
  }
  float2* out = (float2*)d_out;

  k_invstd<<<(4416 + 255) / 256, 256>>>(mstd);

  const int smem = (288 + 98 * 64) * (int)sizeof(float2);  // ~52.5 KB
  cudaFuncSetAttribute(k_fused, cudaFuncAttributeMaxDynamicSharedMemorySize, smem);
  k_fused<<<B, 256, smem>>>(act, wts, out);
}